// round 15
// baseline (speedup 1.0000x reference)
#include <cuda_runtime.h>

typedef unsigned long long ull;

// Scratch (allocation-free rule: __device__ globals; zero-initialized)
__device__ float g_hbuf[16 * 32 * 256];  // conv output h (b,c,l)
__device__ float g_psum[32 * 128];       // BN partial sums  [c][slot]
__device__ float g_psum2[32 * 128];      // BN partial sumsq
__device__ unsigned g_bdone[16];         // per-batch phase-A arrival counters
__device__ unsigned g_bar2, g_fin;

__device__ __forceinline__ float ex2f(float x) {
    float y;
    asm("ex2.approx.ftz.f32 %0, %1;" : "=f"(y) : "f"(x));
    return y;
}
__device__ __forceinline__ ull pk(float a, float b) {
    ull r; asm("mov.b64 %0, {%1, %2};" : "=l"(r) : "f"(a), "f"(b)); return r;
}
__device__ __forceinline__ void upk(ull x, float& a, float& b) {
    asm("mov.b64 {%0, %1}, %2;" : "=f"(a), "=f"(b) : "l"(x));
}
__device__ __forceinline__ ull fma2(ull a, ull b, ull c) {
    ull r; asm("fma.rn.f32x2 %0, %1, %2, %3;" : "=l"(r) : "l"(a), "l"(b), "l"(c)); return r;
}
__device__ __forceinline__ ull mul2(ull a, ull b) {
    ull r; asm("mul.rn.f32x2 %0, %1, %2;" : "=l"(r) : "l"(a), "l"(b)); return r;
}
__device__ __forceinline__ ull add2(ull a, ull b) {
    ull r; asm("add.rn.f32x2 %0, %1, %2;" : "=l"(r) : "l"(a), "l"(b)); return r;
}
__device__ __forceinline__ float hsum(ull x) {
    float a, b; upk(x, a, b); return a + b;
}

// Full grid barrier over 128 co-resident blocks.
__device__ __forceinline__ void gbar(unsigned* ctr) {
    __threadfence();
    __syncthreads();
    if (threadIdx.x == 0) {
        atomicAdd(ctr, 1u);
        volatile unsigned* p = ctr;
        while (*p < 128u) __nanosleep(32);
        __threadfence();
    }
    __syncthreads();
}

// ---------------------------------------------------------------------------
// ONE persistent kernel. 128 blocks x 512 threads. (R11 structure.)
//  A1: QKV proj + l2norm, thread=(tok, hgg2 of 4 heads).
//  A2: attention, thread=(head, token-QUAD), unroll 4, plain ex2.f32.
//  A3: out projection -> out[:, :, t, :].
//  [per-batch wait: only the 8 sibling blocks of batch b]
//  B: conv + BN psums   [gbar2]  C: stats
//  D: BN+ReLU + linear + subtract -> out slot 8. Epilogue resets counters.
// ---------------------------------------------------------------------------
__global__ void __launch_bounds__(512, 1) k_fused(
    const float* __restrict__ x,
    const float* __restrict__ qw, const float* __restrict__ qb,
    const float* __restrict__ kw, const float* __restrict__ kb,
    const float* __restrict__ vw, const float* __restrict__ vb,
    const float* __restrict__ mw, const float* __restrict__ mb,
    const float* __restrict__ pre,
    const float* __restrict__ cw, const float* __restrict__ cb,
    const float* __restrict__ gamma, const float* __restrict__ beta,
    const float* __restrict__ lw, const float* __restrict__ lb,
    float* __restrict__ out)
{
    extern __shared__ float sm[];
    __shared__ float s_sc[32], s_sh[32];

    const int tid = threadIdx.x;
    const int bid = blockIdx.x;
    const int t = bid & 7;
    const int b = bid >> 3;

    // Phase A smem map
    float* kbuf = sm;                  // [8 h][128 mp][8]  (8192)
    float* vbuf = sm + 8192;           // 8192
    float* qbuf = sm + 16384;          // [8 h][256 tok][4] (8192)
    float* wq = sm + 24576;            // 1024 each
    float* wk = wq + 1024;
    float* wv = wk + 1024;
    float* wm = wv + 1024;
    float* bb = wm + 1024;             // [qb|kb|vb|mb]

    // =================== Phase A1: QKV proj + l2norm (4 heads/thread) ======
    {
        const int tok = tid & 255;
        const int hgg2 = tid >> 8;         // 0 or 1: four heads each

        for (int i = tid; i < 1024; i += 512) {
            wq[i] = qw[i]; wk[i] = kw[i];
            wv[i] = vw[i]; wm[i] = mw[i];
        }
        if (tid < 32) {
            bb[tid] = qb[tid]; bb[32 + tid] = kb[tid];
            bb[64 + tid] = vb[tid]; bb[96 + tid] = mb[tid];
        }

        float xr[32];
        #pragma unroll
        for (int c = 0; c < 32; c++)
            xr[c] = x[((b * 32 + c) * 16 + t) * 256 + tok];

        __syncthreads();

        ull xp[16];
        #pragma unroll
        for (int i = 0; i < 16; i++) xp[i] = pk(xr[2 * i], xr[2 * i + 1]);

        const ulonglong2* wq2 = (const ulonglong2*)wq;
        const ulonglong2* wk2 = (const ulonglong2*)wk;
        const ulonglong2* wv2 = (const ulonglong2*)wv;

        const float QS = 0.5f * 1.4426950408889634f;  // (1/sqrt(hd))*log2(e)
        #pragma unroll
        for (int hh = 0; hh < 4; hh++) {
            const int h = hgg2 * 4 + hh;
            float qv[4], kv[4], vv[4];
            #pragma unroll
            for (int j = 0; j < 4; j++) {
                const int co = h * 4 + j;
                ull a0 = 0, a1 = 0, b0 = 0, b1 = 0, c0 = 0, c1 = 0;
                #pragma unroll
                for (int c4 = 0; c4 < 8; c4++) {
                    ulonglong2 w = wq2[co * 8 + c4];
                    a0 = fma2(xp[2 * c4], w.x, a0);
                    a1 = fma2(xp[2 * c4 + 1], w.y, a1);
                    w = wk2[co * 8 + c4];
                    b0 = fma2(xp[2 * c4], w.x, b0);
                    b1 = fma2(xp[2 * c4 + 1], w.y, b1);
                    w = wv2[co * 8 + c4];
                    c0 = fma2(xp[2 * c4], w.x, c0);
                    c1 = fma2(xp[2 * c4 + 1], w.y, c1);
                }
                qv[j] = hsum(add2(a0, a1)) + bb[co];
                kv[j] = hsum(add2(b0, b1)) + bb[32 + co];
                vv[j] = hsum(add2(c0, c1)) + bb[64 + co];
            }
            float qn = sqrtf(qv[0]*qv[0] + qv[1]*qv[1] + qv[2]*qv[2] + qv[3]*qv[3]);
            float qi = QS / fmaxf(qn, 1e-12f);
            *(float4*)&qbuf[h * 1024 + tok * 4] =
                make_float4(qv[0]*qi, qv[1]*qi, qv[2]*qi, qv[3]*qi);

            float kn = sqrtf(kv[0]*kv[0] + kv[1]*kv[1] + kv[2]*kv[2] + kv[3]*kv[3]);
            float ki = 1.0f / fmaxf(kn, 1e-12f);
            float vn = sqrtf(vv[0]*vv[0] + vv[1]*vv[1] + vv[2]*vv[2] + vv[3]*vv[3]);
            float vi = 1.0f / fmaxf(vn, 1e-12f);

            const int base = h * 1024 + (tok >> 1) * 8 + (tok & 1);
            #pragma unroll
            for (int d = 0; d < 4; d++) {
                kbuf[base + 2 * d] = kv[d] * ki;
                vbuf[base + 2 * d] = vv[d] * vi;
            }
        }
    }
    __syncthreads();

    // =================== Phase A2: attention (4 tokens/thread) =============
    ull oreg[8];                           // 2 o-pairs per token x 4 tokens
    int t0_, h2_;
    {
        const int h2 = tid >> 6;           // head 0..7
        const int t0 = (tid & 63) * 4;     // token quad base
        h2_ = h2; t0_ = t0;

        ull Qs[16];
        #pragma unroll
        for (int i = 0; i < 4; i++) {
            float4 q4 = *(const float4*)&qbuf[h2 * 1024 + (t0 + i) * 4];
            Qs[4 * i + 0] = pk(q4.x, q4.x);
            Qs[4 * i + 1] = pk(q4.y, q4.y);
            Qs[4 * i + 2] = pk(q4.z, q4.z);
            Qs[4 * i + 3] = pk(q4.w, q4.w);
        }

        const ulonglong2* kb2 = (const ulonglong2*)(kbuf + h2 * 1024);
        const ulonglong2* vb2 = (const ulonglong2*)(vbuf + h2 * 1024);

        ull pa[16] = {0,0,0,0, 0,0,0,0, 0,0,0,0, 0,0,0,0};
        ull ss[4]  = {0,0,0,0};
        #pragma unroll 4
        for (int mp = 0; mp < 128; mp++) {
            ulonglong2 KA = kb2[2 * mp];      // (k0 pair, k1 pair)
            ulonglong2 KB = kb2[2 * mp + 1];  // (k2 pair, k3 pair)
            ulonglong2 VA = vb2[2 * mp];
            ulonglong2 VB = vb2[2 * mp + 1];
            ull pp[4];
            #pragma unroll
            for (int i = 0; i < 4; i++) {
                ull s = mul2(Qs[4 * i], KA.x);
                s = fma2(Qs[4 * i + 1], KA.y, s);
                s = fma2(Qs[4 * i + 2], KB.x, s);
                s = fma2(Qs[4 * i + 3], KB.y, s);
                float s0, s1; upk(s, s0, s1);
                pp[i] = pk(ex2f(s0), ex2f(s1));
            }
            #pragma unroll
            for (int i = 0; i < 4; i++) {
                ss[i] = add2(ss[i], pp[i]);
                pa[4 * i + 0] = fma2(pp[i], VA.x, pa[4 * i + 0]);
                pa[4 * i + 1] = fma2(pp[i], VA.y, pa[4 * i + 1]);
                pa[4 * i + 2] = fma2(pp[i], VB.x, pa[4 * i + 2]);
                pa[4 * i + 3] = fma2(pp[i], VB.y, pa[4 * i + 3]);
            }
        }
        #pragma unroll
        for (int i = 0; i < 4; i++) {
            float inv = 1.0f / hsum(ss[i]);
            oreg[2 * i]     = pk(hsum(pa[4 * i]) * inv,     hsum(pa[4 * i + 1]) * inv);
            oreg[2 * i + 1] = pk(hsum(pa[4 * i + 2]) * inv, hsum(pa[4 * i + 3]) * inv);
        }
    }

    // =================== Phase A3: exchange + out projection ===============
    __syncthreads();                       // kbuf/vbuf/qbuf reads done
    {
        ull* osm = (ull*)sm;               // [256 tok][17] ull (16 used)
        #pragma unroll
        for (int i = 0; i < 4; i++) {
            osm[(t0_ + i) * 17 + 2 * h2_]     = oreg[2 * i];
            osm[(t0_ + i) * 17 + 2 * h2_ + 1] = oreg[2 * i + 1];
        }
        __syncthreads();

        const int tok = tid & 255;
        const int cg3 = tid >> 8;          // 0/1: 16 co each
        ull ovv[16];
        #pragma unroll
        for (int i = 0; i < 16; i++) ovv[i] = osm[tok * 17 + i];

        const ull* wmu = (const ull*)wm;
        #pragma unroll
        for (int j = 0; j < 16; j++) {
            const int co = cg3 * 16 + j;
            ull a0 = 0, a1 = 0;
            #pragma unroll
            for (int i = 0; i < 16; i += 2) {
                a0 = fma2(ovv[i],     wmu[co * 16 + i],     a0);
                a1 = fma2(ovv[i + 1], wmu[co * 16 + i + 1], a1);
            }
            out[((b * 32 + co) * 9 + t) * 256 + tok] = hsum(add2(a0, a1)) + bb[96 + co];
        }
    }

    // ---- per-batch wait: only the 8 sibling blocks of batch b matter ------
    __threadfence();
    __syncthreads();
    if (tid == 0) {
        atomicAdd(&g_bdone[b], 1u);
        volatile unsigned* p = &g_bdone[b];
        while (*p < 8u) __nanosleep(32);
        __threadfence();
    }
    __syncthreads();

    // ======================= Phase B: conv + psums =========================
    {
        float* slab = sm;                  // [288 cikt][32 toks]
        float* cws  = sm + 9216;           // [288 cikt][34]
        const int bB = bid >> 3, tq = bid & 7;
        const int tok0 = tq * 32;

        #pragma unroll
        for (int idx = tid; idx < 9216; idx += 512) {
            int cikt = idx >> 5, ti2 = idx & 31;
            int ci = cikt / 9, kt = cikt - ci * 9;
            float v = (kt < 8) ? out[((bB * 32 + ci) * 9 + kt) * 256 + tok0 + ti2]
                               : pre[ci * 256 + tok0 + ti2];
            slab[idx] = v;
        }
        #pragma unroll
        for (int idx = tid; idx < 9216; idx += 512) {
            int co = idx / 288, cikt = idx - co * 288;
            cws[cikt * 34 + co] = cw[idx];
        }
        __syncthreads();

        const int ti2 = tid & 31, cg = tid >> 5;   // warp = cg (co pair)
        const int co = 2 * cg;
        ull acc = pk(cb[co], cb[co + 1]);
        const ull* cwsu = (const ull*)cws;
        #pragma unroll 9
        for (int ckt = 0; ckt < 288; ckt++) {
            float v = slab[ckt * 32 + ti2];
            acc = fma2(pk(v, v), cwsu[ckt * 17 + cg], acc);
        }
        float h0, h1; upk(acc, h0, h1);
        const int gtok = tok0 + ti2;
        g_hbuf[(bB * 32 + co) * 256 + gtok]     = h0;
        g_hbuf[(bB * 32 + co + 1) * 256 + gtok] = h1;

        float s0 = h0, q0 = h0 * h0, s1 = h1, q1 = h1 * h1;
        #pragma unroll
        for (int off = 16; off; off >>= 1) {
            s0 += __shfl_down_sync(0xffffffffu, s0, off);
            q0 += __shfl_down_sync(0xffffffffu, q0, off);
            s1 += __shfl_down_sync(0xffffffffu, s1, off);
            q1 += __shfl_down_sync(0xffffffffu, q1, off);
        }
        if (ti2 == 0) {
            g_psum [co * 128 + bid] = s0;        g_psum2[co * 128 + bid] = q0;
            g_psum [(co + 1) * 128 + bid] = s1;  g_psum2[(co + 1) * 128 + bid] = q1;
        }
    }

    gbar(&g_bar2);

    // ======================= Phase C: BN stats =============================
    {
        float* sred  = sm;           // [32 co][16 part]
        float* sred2 = sm + 512;
        const int co = tid >> 4, part = tid & 15;
        float s = 0.f, s2 = 0.f;
        #pragma unroll
        for (int i = 0; i < 8; i++) {
            s  += g_psum [co * 128 + part * 8 + i];
            s2 += g_psum2[co * 128 + part * 8 + i];
        }
        sred[co * 16 + part] = s; sred2[co * 16 + part] = s2;
        __syncthreads();
        if (tid < 32) {
            float S = 0.f, S2 = 0.f;
            #pragma unroll
            for (int p = 0; p < 16; p++) { S += sred[tid * 16 + p]; S2 += sred2[tid * 16 + p]; }
            float mean = S * (1.0f / 4096.0f);
            float var = S2 * (1.0f / 4096.0f) - mean * mean;
            float rstd = rsqrtf(var + 1e-5f);
            float sc = rstd * gamma[tid];
            s_sc[tid] = sc;
            s_sh[tid] = beta[tid] - mean * sc;
        }
        __syncthreads();
    }

    // ======================= Phase D: BN+ReLU + linear =====================
    {
        float* hbn = sm;             // [32][256]
        float* lws = sm + 8192;      // [32][260]
        const int lt = bid & 7;
        const int bD = bid >> 3;

        #pragma unroll
        for (int idx = tid; idx < 8192; idx += 512) {
            int c = idx >> 8;
            float v = g_hbuf[(bD * 32 + c) * 256 + (idx & 255)];
            hbn[idx] = fmaxf(v * s_sc[c] + s_sh[c], 0.f);
        }
        #pragma unroll
        for (int idx = tid; idx < 8192; idx += 512) {
            int r = idx >> 8, col = idx & 255;
            lws[r * 260 + col] = lw[(lt * 32 + r) * 256 + col];
        }
        __syncthreads();

        const int lane = tid & 31, cq = tid >> 5;   // cq in [0,16)
        const int c0 = 2 * cq;
        ull acc0 = 0, acc1 = 0;
        const ulonglong2* wrow = (const ulonglong2*)&lws[lane * 260];
        const ulonglong2* h0 = (const ulonglong2*)&hbn[c0 * 256];
        const ulonglong2* h1 = (const ulonglong2*)&hbn[(c0 + 1) * 256];
        #pragma unroll 8
        for (int l4 = 0; l4 < 64; l4++) {
            ulonglong2 w = wrow[l4];
            ulonglong2 a = h0[l4], bq = h1[l4];
            acc0 = fma2(w.x, a.x,  acc0); acc0 = fma2(w.y, a.y,  acc0);
            acc1 = fma2(w.x, bq.x, acc1); acc1 = fma2(w.y, bq.y, acc1);
        }

        const int lp = lt * 32 + lane;
        const float lbv = lb[lp];
        {
            int base0 = (bD * 32 + c0) * 9;
            out[(base0 + 8) * 256 + lp] = out[(base0 + 2) * 256 + lp] - (hsum(acc0) + lbv);
            int base1 = (bD * 32 + c0 + 1) * 9;
            out[(base1 + 8) * 256 + lp] = out[(base1 + 2) * 256 + lp] - (hsum(acc1) + lbv);
        }
    }

    // ---- epilogue: last block resets all counters for next launch ----
    __syncthreads();
    if (tid == 0) {
        unsigned old = atomicAdd(&g_fin, 1u);
        if (old == 127u) {
            #pragma unroll
            for (int i = 0; i < 16; i++) atomicExch(&g_bdone[i], 0u);
            atomicExch(&g_bar2, 0u);
            atomicExch(&g_fin, 0u);
        }
    }
}

// ---------------------------------------------------------------------------
extern "C" void kernel_launch(void* const* d_in, const int* in_sizes, int n_in,
                              void* d_out, int out_size)
{
    const float* x     = (const float*)d_in[0];
    const float* qw    = (const float*)d_in[1];
    const float* qb    = (const float*)d_in[2];
    const float* kw    = (const float*)d_in[3];
    const float* kb    = (const float*)d_in[4];
    const float* vw    = (const float*)d_in[5];
    const float* vb    = (const float*)d_in[6];
    const float* mw    = (const float*)d_in[7];
    const float* mb    = (const float*)d_in[8];
    const float* pre   = (const float*)d_in[9];
    const float* cw    = (const float*)d_in[10];
    const float* cb    = (const float*)d_in[11];
    const float* gamma = (const float*)d_in[12];
    const float* beta  = (const float*)d_in[13];
    const float* lw    = (const float*)d_in[14];
    const float* lb    = (const float*)d_in[15];
    float* out = (float*)d_out;

    const int smem = (8192 + 8192 + 8192 + 4096 + 128) * 4;   // 115200 B
    cudaFuncSetAttribute(k_fused, cudaFuncAttributeMaxDynamicSharedMemorySize, smem);

    k_fused<<<128, 512, smem>>>(x, qw, qb, kw, kb, vw, vb, mw, mb,
                                pre, cw, cb, gamma, beta, lw, lb, out);
}

// round 16
// speedup vs baseline: 1.0354x; 1.0354x over previous
#include <cuda_runtime.h>

typedef unsigned long long ull;

// Scratch (allocation-free rule: __device__ globals; zero-initialized)
__device__ float g_hbuf[16 * 32 * 256];  // conv output h (b,c,l)
__device__ float g_psum[32 * 128];       // BN partial sums  [c][slot]
__device__ float g_psum2[32 * 128];      // BN partial sumsq
__device__ unsigned g_bar1, g_bar2, g_fin;

__device__ __forceinline__ float ex2f(float x) {
    float y;
    asm("ex2.approx.ftz.f32 %0, %1;" : "=f"(y) : "f"(x));
    return y;
}
__device__ __forceinline__ ull pk(float a, float b) {
    ull r; asm("mov.b64 %0, {%1, %2};" : "=l"(r) : "f"(a), "f"(b)); return r;
}
__device__ __forceinline__ void upk(ull x, float& a, float& b) {
    asm("mov.b64 {%0, %1}, %2;" : "=f"(a), "=f"(b) : "l"(x));
}
__device__ __forceinline__ ull fma2(ull a, ull b, ull c) {
    ull r; asm("fma.rn.f32x2 %0, %1, %2, %3;" : "=l"(r) : "l"(a), "l"(b), "l"(c)); return r;
}
__device__ __forceinline__ ull mul2(ull a, ull b) {
    ull r; asm("mul.rn.f32x2 %0, %1, %2;" : "=l"(r) : "l"(a), "l"(b)); return r;
}
__device__ __forceinline__ ull add2(ull a, ull b) {
    ull r; asm("add.rn.f32x2 %0, %1, %2;" : "=l"(r) : "l"(a), "l"(b)); return r;
}
__device__ __forceinline__ float hsum(ull x) {
    float a, b; upk(x, a, b); return a + b;
}

// Grid barrier over 128 co-resident blocks (one per SM wave).
__device__ __forceinline__ void gbar(unsigned* ctr) {
    __threadfence();
    __syncthreads();
    if (threadIdx.x == 0) {
        atomicAdd(ctr, 1u);
        volatile unsigned* p = ctr;
        while (*p < 128u) __nanosleep(32);
        __threadfence();
    }
    __syncthreads();
}

// ---------------------------------------------------------------------------
// ONE persistent kernel. 128 blocks x 512 threads. (Champion R11 structure.)
//  A1: QKV proj + l2norm, thread=(tok, hgg2 of 4 heads).
//  A2: attention, thread=(head, token-QUAD), unroll 2, plain ex2.f32.
//  A3: out projection -> out[:, :, t, :].
//  [gbar1]  B: conv + BN psums   [gbar2]  C: stats
//  D: BN+ReLU + linear (dual accumulator chains) + subtract -> out slot 8.
// ---------------------------------------------------------------------------
__global__ void __launch_bounds__(512, 1) k_fused(
    const float* __restrict__ x,
    const float* __restrict__ qw, const float* __restrict__ qb,
    const float* __restrict__ kw, const float* __restrict__ kb,
    const float* __restrict__ vw, const float* __restrict__ vb,
    const float* __restrict__ mw, const float* __restrict__ mb,
    const float* __restrict__ pre,
    const float* __restrict__ cw, const float* __restrict__ cb,
    const float* __restrict__ gamma, const float* __restrict__ beta,
    const float* __restrict__ lw, const float* __restrict__ lb,
    float* __restrict__ out)
{
    extern __shared__ float sm[];
    __shared__ float s_sc[32], s_sh[32];

    const int tid = threadIdx.x;
    const int bid = blockIdx.x;
    const int t = bid & 7;
    const int b = bid >> 3;

    // Phase A smem map
    float* kbuf = sm;                  // [8 h][128 mp][8]  (8192)
    float* vbuf = sm + 8192;           // 8192
    float* qbuf = sm + 16384;          // [8 h][256 tok][4] (8192)
    float* wq = sm + 24576;            // 1024 each
    float* wk = wq + 1024;
    float* wv = wk + 1024;
    float* wm = wv + 1024;
    float* bb = wm + 1024;             // [qb|kb|vb|mb]

    // =================== Phase A1: QKV proj + l2norm (4 heads/thread) ======
    {
        const int tok = tid & 255;
        const int hgg2 = tid >> 8;         // 0 or 1: four heads each

        for (int i = tid; i < 1024; i += 512) {
            wq[i] = qw[i]; wk[i] = kw[i];
            wv[i] = vw[i]; wm[i] = mw[i];
        }
        if (tid < 32) {
            bb[tid] = qb[tid]; bb[32 + tid] = kb[tid];
            bb[64 + tid] = vb[tid]; bb[96 + tid] = mb[tid];
        }

        float xr[32];
        #pragma unroll
        for (int c = 0; c < 32; c++)
            xr[c] = x[((b * 32 + c) * 16 + t) * 256 + tok];

        __syncthreads();

        ull xp[16];
        #pragma unroll
        for (int i = 0; i < 16; i++) xp[i] = pk(xr[2 * i], xr[2 * i + 1]);

        const ulonglong2* wq2 = (const ulonglong2*)wq;
        const ulonglong2* wk2 = (const ulonglong2*)wk;
        const ulonglong2* wv2 = (const ulonglong2*)wv;

        const float QS = 0.5f * 1.4426950408889634f;  // (1/sqrt(hd))*log2(e)
        #pragma unroll
        for (int hh = 0; hh < 4; hh++) {
            const int h = hgg2 * 4 + hh;
            float qv[4], kv[4], vv[4];
            #pragma unroll
            for (int j = 0; j < 4; j++) {
                const int co = h * 4 + j;
                ull a0 = 0, a1 = 0, b0 = 0, b1 = 0, c0 = 0, c1 = 0;
                #pragma unroll
                for (int c4 = 0; c4 < 8; c4++) {
                    ulonglong2 w = wq2[co * 8 + c4];
                    a0 = fma2(xp[2 * c4], w.x, a0);
                    a1 = fma2(xp[2 * c4 + 1], w.y, a1);
                    w = wk2[co * 8 + c4];
                    b0 = fma2(xp[2 * c4], w.x, b0);
                    b1 = fma2(xp[2 * c4 + 1], w.y, b1);
                    w = wv2[co * 8 + c4];
                    c0 = fma2(xp[2 * c4], w.x, c0);
                    c1 = fma2(xp[2 * c4 + 1], w.y, c1);
                }
                qv[j] = hsum(add2(a0, a1)) + bb[co];
                kv[j] = hsum(add2(b0, b1)) + bb[32 + co];
                vv[j] = hsum(add2(c0, c1)) + bb[64 + co];
            }
            float qn = sqrtf(qv[0]*qv[0] + qv[1]*qv[1] + qv[2]*qv[2] + qv[3]*qv[3]);
            float qi = QS / fmaxf(qn, 1e-12f);
            *(float4*)&qbuf[h * 1024 + tok * 4] =
                make_float4(qv[0]*qi, qv[1]*qi, qv[2]*qi, qv[3]*qi);

            float kn = sqrtf(kv[0]*kv[0] + kv[1]*kv[1] + kv[2]*kv[2] + kv[3]*kv[3]);
            float ki = 1.0f / fmaxf(kn, 1e-12f);
            float vn = sqrtf(vv[0]*vv[0] + vv[1]*vv[1] + vv[2]*vv[2] + vv[3]*vv[3]);
            float vi = 1.0f / fmaxf(vn, 1e-12f);

            const int base = h * 1024 + (tok >> 1) * 8 + (tok & 1);
            #pragma unroll
            for (int d = 0; d < 4; d++) {
                kbuf[base + 2 * d] = kv[d] * ki;
                vbuf[base + 2 * d] = vv[d] * vi;
            }
        }
    }
    __syncthreads();

    // =================== Phase A2: attention (4 tokens/thread) =============
    ull oreg[8];                           // 2 o-pairs per token x 4 tokens
    int t0_, h2_;
    {
        const int h2 = tid >> 6;           // head 0..7
        const int t0 = (tid & 63) * 4;     // token quad base
        h2_ = h2; t0_ = t0;

        ull Qs[16];
        #pragma unroll
        for (int i = 0; i < 4; i++) {
            float4 q4 = *(const float4*)&qbuf[h2 * 1024 + (t0 + i) * 4];
            Qs[4 * i + 0] = pk(q4.x, q4.x);
            Qs[4 * i + 1] = pk(q4.y, q4.y);
            Qs[4 * i + 2] = pk(q4.z, q4.z);
            Qs[4 * i + 3] = pk(q4.w, q4.w);
        }

        const ulonglong2* kb2 = (const ulonglong2*)(kbuf + h2 * 1024);
        const ulonglong2* vb2 = (const ulonglong2*)(vbuf + h2 * 1024);

        ull pa[16] = {0,0,0,0, 0,0,0,0, 0,0,0,0, 0,0,0,0};
        ull ss[4]  = {0,0,0,0};
        #pragma unroll 2
        for (int mp = 0; mp < 128; mp++) {
            // batched loads up front (MLP; all uniform broadcasts)
            ulonglong2 KA = kb2[2 * mp];      // (k0 pair, k1 pair)
            ulonglong2 KB = kb2[2 * mp + 1];  // (k2 pair, k3 pair)
            ulonglong2 VA = vb2[2 * mp];
            ulonglong2 VB = vb2[2 * mp + 1];
            ull pp[4];
            #pragma unroll
            for (int i = 0; i < 4; i++) {
                ull s = mul2(Qs[4 * i], KA.x);
                s = fma2(Qs[4 * i + 1], KA.y, s);
                s = fma2(Qs[4 * i + 2], KB.x, s);
                s = fma2(Qs[4 * i + 3], KB.y, s);
                float s0, s1; upk(s, s0, s1);
                pp[i] = pk(ex2f(s0), ex2f(s1));
            }
            #pragma unroll
            for (int i = 0; i < 4; i++) {
                ss[i] = add2(ss[i], pp[i]);
                pa[4 * i + 0] = fma2(pp[i], VA.x, pa[4 * i + 0]);
                pa[4 * i + 1] = fma2(pp[i], VA.y, pa[4 * i + 1]);
                pa[4 * i + 2] = fma2(pp[i], VB.x, pa[4 * i + 2]);
                pa[4 * i + 3] = fma2(pp[i], VB.y, pa[4 * i + 3]);
            }
        }
        #pragma unroll
        for (int i = 0; i < 4; i++) {
            float inv = 1.0f / hsum(ss[i]);
            oreg[2 * i]     = pk(hsum(pa[4 * i]) * inv,     hsum(pa[4 * i + 1]) * inv);
            oreg[2 * i + 1] = pk(hsum(pa[4 * i + 2]) * inv, hsum(pa[4 * i + 3]) * inv);
        }
    }

    // =================== Phase A3: exchange + out projection ===============
    __syncthreads();                       // kbuf/vbuf/qbuf reads done
    {
        ull* osm = (ull*)sm;               // [256 tok][17] ull (16 used)
        #pragma unroll
        for (int i = 0; i < 4; i++) {
            osm[(t0_ + i) * 17 + 2 * h2_]     = oreg[2 * i];
            osm[(t0_ + i) * 17 + 2 * h2_ + 1] = oreg[2 * i + 1];
        }
        __syncthreads();

        const int tok = tid & 255;
        const int cg3 = tid >> 8;          // 0/1: 16 co each
        ull ovv[16];
        #pragma unroll
        for (int i = 0; i < 16; i++) ovv[i] = osm[tok * 17 + i];

        const ull* wmu = (const ull*)wm;
        #pragma unroll
        for (int j = 0; j < 16; j++) {
            const int co = cg3 * 16 + j;
            ull a0 = 0, a1 = 0;
            #pragma unroll
            for (int i = 0; i < 16; i += 2) {
                a0 = fma2(ovv[i],     wmu[co * 16 + i],     a0);
                a1 = fma2(ovv[i + 1], wmu[co * 16 + i + 1], a1);
            }
            out[((b * 32 + co) * 9 + t) * 256 + tok] = hsum(add2(a0, a1)) + bb[96 + co];
        }
    }

    gbar(&g_bar1);

    // ======================= Phase B: conv + psums =========================
    {
        float* slab = sm;                  // [288 cikt][32 toks]
        float* cws  = sm + 9216;           // [288 cikt][34]
        const int bB = bid >> 3, tq = bid & 7;
        const int tok0 = tq * 32;

        #pragma unroll
        for (int idx = tid; idx < 9216; idx += 512) {
            int cikt = idx >> 5, ti2 = idx & 31;
            int ci = cikt / 9, kt = cikt - ci * 9;
            float v = (kt < 8) ? out[((bB * 32 + ci) * 9 + kt) * 256 + tok0 + ti2]
                               : pre[ci * 256 + tok0 + ti2];
            slab[idx] = v;
        }
        #pragma unroll
        for (int idx = tid; idx < 9216; idx += 512) {
            int co = idx / 288, cikt = idx - co * 288;
            cws[cikt * 34 + co] = cw[idx];
        }
        __syncthreads();

        const int ti2 = tid & 31, cg = tid >> 5;   // warp = cg (co pair)
        const int co = 2 * cg;
        ull acc = pk(cb[co], cb[co + 1]);
        const ull* cwsu = (const ull*)cws;
        #pragma unroll 9
        for (int ckt = 0; ckt < 288; ckt++) {
            float v = slab[ckt * 32 + ti2];
            acc = fma2(pk(v, v), cwsu[ckt * 17 + cg], acc);
        }
        float h0, h1; upk(acc, h0, h1);
        const int gtok = tok0 + ti2;
        g_hbuf[(bB * 32 + co) * 256 + gtok]     = h0;
        g_hbuf[(bB * 32 + co + 1) * 256 + gtok] = h1;

        float s0 = h0, q0 = h0 * h0, s1 = h1, q1 = h1 * h1;
        #pragma unroll
        for (int off = 16; off; off >>= 1) {
            s0 += __shfl_down_sync(0xffffffffu, s0, off);
            q0 += __shfl_down_sync(0xffffffffu, q0, off);
            s1 += __shfl_down_sync(0xffffffffu, s1, off);
            q1 += __shfl_down_sync(0xffffffffu, q1, off);
        }
        if (ti2 == 0) {
            g_psum [co * 128 + bid] = s0;        g_psum2[co * 128 + bid] = q0;
            g_psum [(co + 1) * 128 + bid] = s1;  g_psum2[(co + 1) * 128 + bid] = q1;
        }
    }

    gbar(&g_bar2);

    // ======================= Phase C: BN stats =============================
    {
        float* sred  = sm;           // [32 co][16 part]
        float* sred2 = sm + 512;
        const int co = tid >> 4, part = tid & 15;
        float s = 0.f, s2 = 0.f;
        #pragma unroll
        for (int i = 0; i < 8; i++) {
            s  += g_psum [co * 128 + part * 8 + i];
            s2 += g_psum2[co * 128 + part * 8 + i];
        }
        sred[co * 16 + part] = s; sred2[co * 16 + part] = s2;
        __syncthreads();
        if (tid < 32) {
            float S = 0.f, S2 = 0.f;
            #pragma unroll
            for (int p = 0; p < 16; p++) { S += sred[tid * 16 + p]; S2 += sred2[tid * 16 + p]; }
            float mean = S * (1.0f / 4096.0f);
            float var = S2 * (1.0f / 4096.0f) - mean * mean;
            float rstd = rsqrtf(var + 1e-5f);
            float sc = rstd * gamma[tid];
            s_sc[tid] = sc;
            s_sh[tid] = beta[tid] - mean * sc;
        }
        __syncthreads();
    }

    // ======================= Phase D: BN+ReLU + linear =====================
    {
        float* hbn = sm;             // [32][256]
        float* lws = sm + 8192;      // [32][260]
        const int lt = bid & 7;
        const int bD = bid >> 3;

        #pragma unroll
        for (int idx = tid; idx < 8192; idx += 512) {
            int c = idx >> 8;
            float v = g_hbuf[(bD * 32 + c) * 256 + (idx & 255)];
            hbn[idx] = fmaxf(v * s_sc[c] + s_sh[c], 0.f);
        }
        #pragma unroll
        for (int idx = tid; idx < 8192; idx += 512) {
            int r = idx >> 8, col = idx & 255;
            lws[r * 260 + col] = lw[(lt * 32 + r) * 256 + col];
        }
        __syncthreads();

        const int lane = tid & 31, cq = tid >> 5;   // cq in [0,16)
        const int c0 = 2 * cq;
        // dual independent chains per channel (halved dependent-fma2 depth)
        ull a0a = 0, a0b = 0, a1a = 0, a1b = 0;
        const ulonglong2* wrow = (const ulonglong2*)&lws[lane * 260];
        const ulonglong2* h0 = (const ulonglong2*)&hbn[c0 * 256];
        const ulonglong2* h1 = (const ulonglong2*)&hbn[(c0 + 1) * 256];
        #pragma unroll 8
        for (int l4 = 0; l4 < 64; l4++) {
            ulonglong2 w = wrow[l4];
            ulonglong2 a = h0[l4], bq = h1[l4];
            a0a = fma2(w.x, a.x,  a0a); a0b = fma2(w.y, a.y,  a0b);
            a1a = fma2(w.x, bq.x, a1a); a1b = fma2(w.y, bq.y, a1b);
        }
        ull acc0 = add2(a0a, a0b);
        ull acc1 = add2(a1a, a1b);

        const int lp = lt * 32 + lane;
        const float lbv = lb[lp];
        {
            int base0 = (bD * 32 + c0) * 9;
            out[(base0 + 8) * 256 + lp] = out[(base0 + 2) * 256 + lp] - (hsum(acc0) + lbv);
            int base1 = (bD * 32 + c0 + 1) * 9;
            out[(base1 + 8) * 256 + lp] = out[(base1 + 2) * 256 + lp] - (hsum(acc1) + lbv);
        }
    }

    // ---- epilogue: last block resets barrier counters for next launch ----
    __syncthreads();
    if (tid == 0) {
        unsigned old = atomicAdd(&g_fin, 1u);
        if (old == 127u) {
            atomicExch(&g_bar1, 0u);
            atomicExch(&g_bar2, 0u);
            atomicExch(&g_fin, 0u);
        }
    }
}

// ---------------------------------------------------------------------------
extern "C" void kernel_launch(void* const* d_in, const int* in_sizes, int n_in,
                              void* d_out, int out_size)
{
    const float* x     = (const float*)d_in[0];
    const float* qw    = (const float*)d_in[1];
    const float* qb    = (const float*)d_in[2];
    const float* kw    = (const float*)d_in[3];
    const float* kb    = (const float*)d_in[4];
    const float* vw    = (const float*)d_in[5];
    const float* vb    = (const float*)d_in[6];
    const float* mw    = (const float*)d_in[7];
    const float* mb    = (const float*)d_in[8];
    const float* pre   = (const float*)d_in[9];
    const float* cw    = (const float*)d_in[10];
    const float* cb    = (const float*)d_in[11];
    const float* gamma = (const float*)d_in[12];
    const float* beta  = (const float*)d_in[13];
    const float* lw    = (const float*)d_in[14];
    const float* lb    = (const float*)d_in[15];
    float* out = (float*)d_out;

    const int smem = (8192 + 8192 + 8192 + 4096 + 128) * 4;   // 115200 B
    cudaFuncSetAttribute(k_fused, cudaFuncAttributeMaxDynamicSharedMemorySize, smem);

    k_fused<<<128, 512, smem>>>(x, qw, qb, kw, kb, vw, vb, mw, mb,
                                pre, cw, cb, gamma, beta, lw, lb, out);
}